// round 2
// baseline (speedup 1.0000x reference)
#include <cuda_runtime.h>
#include <cstdint>

// ---------------------------------------------------------------------------
// out = concat( relu(A@relu(A@F)), A@(A@G) ), A:[8192,8192] f32, F,G:[8192,64]
// Per layer: one fused GEMM C[8192,128] = A @ Bt^T (Bt K-major [128][8192]),
// relu on cols [0,64). mma.sync.m16n8k8.tf32 (plain sm_103 target — tcgen05
// is unavailable because harness PTX target lacks the 'a' suffix).
// ---------------------------------------------------------------------------

#define NN      8192
#define NB      128
#define MT      64            // M-tile per CTA  -> 128 CTAs
#define KT      32            // K per stage
#define STAGES  4
#define KIT     (NN / KT)     // 256
#define ROWF    36            // padded floats per K-row (conflict-free frags)
#define A_STG_F (MT * ROWF)   // 2304 floats
#define B_STG_F (NB * ROWF)   // 4608 floats
#define STG_F   (A_STG_F + B_STG_F)          // 6912 floats
#define SMEM_BYTES (STAGES * STG_F * 4)      // 110592 B

__device__ float g_bt1[NB * NN];   // layer-1 B operand (K-major, tf32-rounded)
__device__ float g_bt2[NB * NN];   // layer-1 output transposed = layer-2 B

// ---------------------------------------------------------------------------
__device__ __forceinline__ uint32_t smem_u32(const void* p) {
    uint32_t a;
    asm("{ .reg .u64 t; cvta.to.shared.u64 t, %1; cvt.u32.u64 %0, t; }"
        : "=r"(a) : "l"(p));
    return a;
}

__device__ __forceinline__ uint32_t f2tf32(float f) {
    uint32_t u;
    asm("cvt.rna.tf32.f32 %0, %1;" : "=r"(u) : "f"(f));
    return u;
}
__device__ __forceinline__ float f2tf32f(float f) {
    return __uint_as_float(f2tf32(f));
}

#define CP_ASYNC16(dst, src) \
    asm volatile("cp.async.cg.shared.global [%0], [%1], 16;" \
                 :: "r"(dst), "l"(src) : "memory")
#define CP_COMMIT() asm volatile("cp.async.commit_group;" ::: "memory")
#define CP_WAIT2()  asm volatile("cp.async.wait_group 2;" ::: "memory")

__device__ __forceinline__ void mma_tf32(float* c, const uint32_t* a,
                                         const uint32_t* b) {
    asm volatile(
        "mma.sync.aligned.m16n8k8.row.col.f32.tf32.tf32.f32 "
        "{%0,%1,%2,%3}, {%4,%5,%6,%7}, {%8,%9}, {%0,%1,%2,%3};"
        : "+f"(c[0]), "+f"(c[1]), "+f"(c[2]), "+f"(c[3])
        : "r"(a[0]), "r"(a[1]), "r"(a[2]), "r"(a[3]), "r"(b[0]), "r"(b[1]));
}

// ---------------------------------------------------------------------------
// Pack F||G transposed into Bt[128][8192], values rounded to tf32.
// ---------------------------------------------------------------------------
__global__ void pack_bt_kernel(const float* __restrict__ F,
                               const float* __restrict__ G,
                               float* __restrict__ Bt) {
    __shared__ float tile[32][33];
    int kb = blockIdx.x * 32;
    int nb = blockIdx.y * 32;
    int tx = threadIdx.x, ty = threadIdx.y;   // block (32, 8)
    #pragma unroll
    for (int r = ty; r < 32; r += 8) {
        int k = kb + r, n = nb + tx;
        float v = (n < 64) ? F[(size_t)k * 64 + n] : G[(size_t)k * 64 + (n - 64)];
        tile[r][tx] = f2tf32f(v);
    }
    __syncthreads();
    #pragma unroll
    for (int r = ty; r < 32; r += 8) {
        int n = nb + r, k = kb + tx;
        Bt[(size_t)n * NN + k] = tile[tx][r];
    }
}

// ---------------------------------------------------------------------------
// Fused layer GEMM. outT: transposed tf32-rounded (feeds next layer);
// outR: row-major final output. Exactly one is non-null.
// ---------------------------------------------------------------------------
__global__ void __launch_bounds__(256, 1)
gemm_layer(const float* __restrict__ A, const float* __restrict__ Bt,
           float* __restrict__ outT, float* __restrict__ outR) {
    extern __shared__ float smem[];
    const int tid  = threadIdx.x;
    const int lane = tid & 31;
    const int w    = tid >> 5;          // 8 warps
    const int wm   = w & 1;             // 2 warps over M (32 rows each)
    const int wn   = w >> 1;            // 4 warps over N (32 cols each)
    const int m0   = blockIdx.x * MT;
    const uint32_t sbase = smem_u32(smem);

    float acc[2][4][4];
    #pragma unroll
    for (int mi = 0; mi < 2; mi++)
        #pragma unroll
        for (int ni = 0; ni < 4; ni++)
            #pragma unroll
            for (int j = 0; j < 4; j++) acc[mi][ni][j] = 0.f;

    // ---- producer: stage fill (A: 512 chunks, B: 1024 chunks of 16B) ----
    auto issue_stage = [&](int it) {
        const int s = it & (STAGES - 1);
        const int k0 = it * KT;
        const uint32_t abase = sbase + (uint32_t)(s * STG_F) * 4u;
        const uint32_t bbase = abase + A_STG_F * 4u;
        #pragma unroll
        for (int j = 0; j < 2; j++) {
            int ch = tid + 256 * j;
            int row = ch >> 3, cc = ch & 7;
            const float* src = A + (size_t)(m0 + row) * NN + k0 + cc * 4;
            CP_ASYNC16(abase + (uint32_t)(row * ROWF + cc * 4) * 4u, src);
        }
        #pragma unroll
        for (int j = 0; j < 4; j++) {
            int ch = tid + 256 * j;
            int row = ch >> 3, cc = ch & 7;
            const float* src = Bt + (size_t)row * NN + k0 + cc * 4;
            CP_ASYNC16(bbase + (uint32_t)(row * ROWF + cc * 4) * 4u, src);
        }
    };

    #pragma unroll
    for (int it = 0; it < STAGES - 1; it++) { issue_stage(it); CP_COMMIT(); }

    for (int it = 0; it < KIT; it++) {
        CP_WAIT2();
        __syncthreads();
        if (it + STAGES - 1 < KIT) issue_stage(it + STAGES - 1);
        CP_COMMIT();   // empty group in tail keeps wait_group bookkeeping exact

        const int s = it & (STAGES - 1);
        const float* As = smem + s * STG_F;
        const float* Bs = As + A_STG_F;
        const float* aP = As + (wm * 32 + (lane >> 2)) * ROWF + (lane & 3);
        const float* bP = Bs + (wn * 32 + (lane >> 2)) * ROWF + (lane & 3);

        #pragma unroll
        for (int ks = 0; ks < 4; ks++) {
            uint32_t afr[2][4];
            uint32_t bfr[4][2];
            #pragma unroll
            for (int mi = 0; mi < 2; mi++) {
                afr[mi][0] = f2tf32(aP[(mi * 16 + 0) * ROWF + ks * 8 + 0]);
                afr[mi][1] = f2tf32(aP[(mi * 16 + 8) * ROWF + ks * 8 + 0]);
                afr[mi][2] = f2tf32(aP[(mi * 16 + 0) * ROWF + ks * 8 + 4]);
                afr[mi][3] = f2tf32(aP[(mi * 16 + 8) * ROWF + ks * 8 + 4]);
            }
            #pragma unroll
            for (int ni = 0; ni < 4; ni++) {
                bfr[ni][0] = __float_as_uint(bP[ni * 8 * ROWF + ks * 8 + 0]);
                bfr[ni][1] = __float_as_uint(bP[ni * 8 * ROWF + ks * 8 + 4]);
            }
            #pragma unroll
            for (int mi = 0; mi < 2; mi++)
                #pragma unroll
                for (int ni = 0; ni < 4; ni++)
                    mma_tf32(acc[mi][ni], afr[mi], bfr[ni]);
        }
    }

    // ---- epilogue ----
    const int rBase = m0 + wm * 32 + (lane >> 2);
    const int nBase = wn * 32 + (lane & 3) * 2;
    #pragma unroll
    for (int mi = 0; mi < 2; mi++) {
        #pragma unroll
        for (int ni = 0; ni < 4; ni++) {
            #pragma unroll
            for (int j = 0; j < 4; j++) {
                int row = rBase + mi * 16 + (j >> 1) * 8;
                int col = nBase + ni * 8 + (j & 1);
                float v = acc[mi][ni][j];
                if (col < 64) v = fmaxf(v, 0.0f);
                if (outT) outT[(size_t)col * NN + row] = f2tf32f(v);
                else      outR[(size_t)row * NB + col] = v;
            }
        }
    }
}

// ---------------------------------------------------------------------------
extern "C" void kernel_launch(void* const* d_in, const int* in_sizes, int n_in,
                              void* d_out, int out_size) {
    (void)in_sizes; (void)n_in; (void)out_size;
    const float* A = (const float*)d_in[0];
    const float* F = (const float*)d_in[1];
    const float* G = (const float*)d_in[2];
    float* out = (float*)d_out;

    float *bt1 = nullptr, *bt2 = nullptr;
    cudaGetSymbolAddress((void**)&bt1, g_bt1);
    cudaGetSymbolAddress((void**)&bt2, g_bt2);

    cudaFuncSetAttribute(gemm_layer,
                         cudaFuncAttributeMaxDynamicSharedMemorySize, SMEM_BYTES);

    dim3 pb(32, 8), pg(NN / 32, NB / 32);
    pack_bt_kernel<<<pg, pb>>>(F, G, bt1);

    gemm_layer<<<NN / MT, 256, SMEM_BYTES>>>(A, bt1, bt2, nullptr);
    gemm_layer<<<NN / MT, 256, SMEM_BYTES>>>(A, bt2, nullptr, out);
}

// round 3
// speedup vs baseline: 1.0841x; 1.0841x over previous
#include <cuda_runtime.h>
#include <cstdint>

// ---------------------------------------------------------------------------
// out = concat( relu(A@relu(A@F)), A@(A@G) ), A:[8192,8192] f32, F,G:[8192,64]
// Per layer: fused GEMM C[8192,128] = A @ Bt^T, relu on cols [0,64).
// mma.sync.m16n8k8.tf32; A rounded to tf32 in-loop via 2 ALU ops; Bt stored
// K-permuted in GMEM so B fragments load as float4 from smem.
// ---------------------------------------------------------------------------

#define NN      8192
#define NB      128
#define MT      64            // M-tile per CTA -> 128 CTAs
#define KT      32            // K per stage
#define STAGES  4
#define KIT     (NN / KT)     // 256
#define AROW    36            // A smem row pitch (floats), conflict-free LDS.32
#define BROW    48            // B smem row pitch (floats), conflict-free LDS.128
#define A_STG_F (MT * AROW)   // 2304
#define B_STG_F (NB * BROW)   // 6144
#define STG_F   (A_STG_F + B_STG_F)       // 8448 floats
#define SMEM_BYTES (STAGES * STG_F * 4)   // 135168 B

__device__ float g_bt1[NB * NN];   // layer-1 B (K-permuted, tf32-rounded)
__device__ float g_bt2[NB * NN];   // layer-1 out transposed = layer-2 B

// k-permutation within 16-blocks: pos = (k%4)*4 + (k/4)%4
__device__ __forceinline__ int kperm(int k) {
    return (k & ~15) | ((k & 3) << 2) | ((k >> 2) & 3);
}

__device__ __forceinline__ uint32_t smem_u32(const void* p) {
    uint32_t a;
    asm("{ .reg .u64 t; cvta.to.shared.u64 t, %1; cvt.u32.u64 %0, t; }"
        : "=r"(a) : "l"(p));
    return a;
}

// tf32 round-to-nearest-ties-away on raw bits (== cvt.rna.tf32 result bits)
__device__ __forceinline__ uint32_t rna_tf32_bits(float f) {
    return (__float_as_uint(f) + 0x1000u) & 0xFFFFE000u;
}
__device__ __forceinline__ float rna_tf32_f(float f) {
    uint32_t u;
    asm("cvt.rna.tf32.f32 %0, %1;" : "=r"(u) : "f"(f));
    return __uint_as_float(u);
}

#define CP_ASYNC16(dst, src) \
    asm volatile("cp.async.cg.shared.global [%0], [%1], 16;" \
                 :: "r"(dst), "l"(src) : "memory")
#define CP_COMMIT() asm volatile("cp.async.commit_group;" ::: "memory")
#define CP_WAIT2()  asm volatile("cp.async.wait_group 2;" ::: "memory")

__device__ __forceinline__ void mma_tf32(float* c, const uint32_t* a,
                                         const uint32_t* b) {
    asm volatile(
        "mma.sync.aligned.m16n8k8.row.col.f32.tf32.tf32.f32 "
        "{%0,%1,%2,%3}, {%4,%5,%6,%7}, {%8,%9}, {%0,%1,%2,%3};"
        : "+f"(c[0]), "+f"(c[1]), "+f"(c[2]), "+f"(c[3])
        : "r"(a[0]), "r"(a[1]), "r"(a[2]), "r"(a[3]), "r"(b[0]), "r"(b[1]));
}

// ---------------------------------------------------------------------------
// Pack F||G transposed + K-permuted + tf32-rounded into Bt[128][8192]
// ---------------------------------------------------------------------------
__global__ void pack_bt_kernel(const float* __restrict__ F,
                               const float* __restrict__ G,
                               float* __restrict__ Bt) {
    __shared__ float tile[32][33];
    int kb = blockIdx.x * 32;
    int nb = blockIdx.y * 32;
    int tx = threadIdx.x, ty = threadIdx.y;   // block (32, 8)
    #pragma unroll
    for (int r = ty; r < 32; r += 8) {
        int k = kb + r, n = nb + tx;
        float v = (n < 64) ? F[(size_t)k * 64 + n] : G[(size_t)k * 64 + (n - 64)];
        tile[r][tx] = rna_tf32_f(v);
    }
    __syncthreads();
    #pragma unroll
    for (int r = ty; r < 32; r += 8) {
        int n = nb + r, k = kb + tx;
        Bt[(size_t)n * NN + kperm(k)] = tile[tx][r];
    }
}

// ---------------------------------------------------------------------------
// Fused layer GEMM. outT: K-permuted transposed tf32-rounded (next layer's B);
// outR: row-major final output. Exactly one is non-null.
// ---------------------------------------------------------------------------
__global__ void __launch_bounds__(256, 1)
gemm_layer(const float* __restrict__ A, const float* __restrict__ Bt,
           float* __restrict__ outT, float* __restrict__ outR) {
    extern __shared__ float smem[];
    const int tid  = threadIdx.x;
    const int lane = tid & 31;
    const int w    = tid >> 5;          // 8 warps
    const int wm   = w & 1;             // 2 warps over M (32 rows each)
    const int wn   = w >> 1;            // 4 warps over N (32 cols each)
    const int m0   = blockIdx.x * MT;
    const uint32_t sbase = smem_u32(smem);

    float acc[2][4][4];
    #pragma unroll
    for (int mi = 0; mi < 2; mi++)
        #pragma unroll
        for (int ni = 0; ni < 4; ni++)
            #pragma unroll
            for (int j = 0; j < 4; j++) acc[mi][ni][j] = 0.f;

    // ---- producer: A 512 chunks, B 1024 chunks of 16B per stage ----
    auto issue_stage = [&](int it) {
        const int s = it & (STAGES - 1);
        const int k0 = it * KT;
        const uint32_t abase = sbase + (uint32_t)(s * STG_F) * 4u;
        const uint32_t bbase = abase + A_STG_F * 4u;
        #pragma unroll
        for (int j = 0; j < 2; j++) {
            int ch = tid + 256 * j;
            int row = ch >> 3, cc = ch & 7;
            const float* src = A + (size_t)(m0 + row) * NN + k0 + cc * 4;
            CP_ASYNC16(abase + (uint32_t)(row * AROW + cc * 4) * 4u, src);
        }
        #pragma unroll
        for (int j = 0; j < 4; j++) {
            int ch = tid + 256 * j;
            int row = ch >> 3, cc = ch & 7;
            const float* src = Bt + (size_t)row * NN + k0 + cc * 4;
            CP_ASYNC16(bbase + (uint32_t)(row * BROW + cc * 4) * 4u, src);
        }
    };

    #pragma unroll
    for (int it = 0; it < STAGES - 1; it++) { issue_stage(it); CP_COMMIT(); }

    const int r4 = lane >> 2;       // 0..7
    const int c4 = lane & 3;        // 0..3

    for (int it = 0; it < KIT; it++) {
        CP_WAIT2();
        __syncthreads();
        if (it + STAGES - 1 < KIT) issue_stage(it + STAGES - 1);
        CP_COMMIT();

        const int s = it & (STAGES - 1);
        const float* As = smem + s * STG_F;
        const float* Bs = As + A_STG_F;
        const float*  aP = As + (wm * 32 + r4) * AROW + c4;
        const float4* bP = (const float4*)(Bs + (wn * 32 + r4) * BROW) + c4;

        // ---- load + round ALL stage fragments, then MMA burst ----
        uint32_t a[4][8];                      // rows {r4+8g}, k = c4+4j
        #pragma unroll
        for (int g = 0; g < 4; g++)
            #pragma unroll
            for (int j = 0; j < 8; j++)
                a[g][j] = (__float_as_uint(aP[g * 8 * AROW + 4 * j]) + 0x1000u)
                          & 0xFFFFE000u;

        float4 b[4][2];                        // rows {r4+8g}, kb halves
        #pragma unroll
        for (int g = 0; g < 4; g++)
            #pragma unroll
            for (int kb = 0; kb < 2; kb++)
                b[g][kb] = bP[g * 8 * (BROW / 4) + kb * 4];

        #pragma unroll
        for (int ks = 0; ks < 4; ks++) {
            uint32_t af0[4] = { a[0][2 * ks], a[1][2 * ks],
                                a[0][2 * ks + 1], a[1][2 * ks + 1] };
            uint32_t af1[4] = { a[2][2 * ks], a[3][2 * ks],
                                a[2][2 * ks + 1], a[3][2 * ks + 1] };
            #pragma unroll
            for (int ni = 0; ni < 4; ni++) {
                const float4 bb = b[ni][ks >> 1];
                uint32_t bf[2];
                if (ks & 1) { bf[0] = __float_as_uint(bb.z);
                              bf[1] = __float_as_uint(bb.w); }
                else        { bf[0] = __float_as_uint(bb.x);
                              bf[1] = __float_as_uint(bb.y); }
                mma_tf32(acc[0][ni], af0, bf);
                mma_tf32(acc[1][ni], af1, bf);
            }
        }
    }

    // ---- epilogue ----
    const int rBase = m0 + wm * 32 + r4;
    const int nBase = wn * 32 + c4 * 2;
    #pragma unroll
    for (int mi = 0; mi < 2; mi++) {
        #pragma unroll
        for (int ni = 0; ni < 4; ni++) {
            #pragma unroll
            for (int j = 0; j < 4; j++) {
                int row = rBase + mi * 16 + (j >> 1) * 8;
                int col = nBase + ni * 8 + (j & 1);
                float v = acc[mi][ni][j];
                if (col < 64) v = fmaxf(v, 0.0f);
                if (outT) outT[(size_t)col * NN + kperm(row)] = rna_tf32_f(v);
                else      outR[(size_t)row * NB + col] = v;
            }
        }
    }
}

// ---------------------------------------------------------------------------
extern "C" void kernel_launch(void* const* d_in, const int* in_sizes, int n_in,
                              void* d_out, int out_size) {
    (void)in_sizes; (void)n_in; (void)out_size;
    const float* A = (const float*)d_in[0];
    const float* F = (const float*)d_in[1];
    const float* G = (const float*)d_in[2];
    float* out = (float*)d_out;

    float *bt1 = nullptr, *bt2 = nullptr;
    cudaGetSymbolAddress((void**)&bt1, g_bt1);
    cudaGetSymbolAddress((void**)&bt2, g_bt2);

    cudaFuncSetAttribute(gemm_layer,
                         cudaFuncAttributeMaxDynamicSharedMemorySize, SMEM_BYTES);

    dim3 pb(32, 8), pg(NN / 32, NB / 32);
    pack_bt_kernel<<<pg, pb>>>(F, G, bt1);

    gemm_layer<<<NN / MT, 256, SMEM_BYTES>>>(A, bt1, bt2, nullptr);
    gemm_layer<<<NN / MT, 256, SMEM_BYTES>>>(A, bt2, nullptr, out);
}

// round 4
// speedup vs baseline: 1.4106x; 1.3012x over previous
#include <cuda_runtime.h>
#include <cstdint>

// ---------------------------------------------------------------------------
// out = concat( relu(A@relu(A@F)), A@(A@G) ), A:[8192,8192] f32, F,G:[8192,64]
// Per layer: fused GEMM C[8192,128] = A @ Bt^T, relu on cols [0,64).
// mma.sync.m16n8k8.tf32, register-double-buffered fragments (LDS hidden
// under MMA burst), A rounded via single IADD (+0x1000; HW truncates).
// ---------------------------------------------------------------------------

#define NN      8192
#define NB      128
#define MT      64            // M-tile per CTA -> 128 CTAs
#define KT      32            // K per stage
#define STAGES  4
#define KIT     (NN / KT)     // 256
#define AROW    36            // A smem row pitch (floats)
#define BROW    48            // B smem row pitch (floats), LDS.128-friendly
#define A_STG_F (MT * AROW)   // 2304
#define B_STG_F (NB * BROW)   // 6144
#define STG_F   (A_STG_F + B_STG_F)       // 8448 floats
#define SMEM_BYTES (STAGES * STG_F * 4)   // 135168 B

__device__ float g_bt1[NB * NN];   // layer-1 B (K-permuted, tf32-rounded)
__device__ float g_bt2[NB * NN];   // layer-1 out transposed = layer-2 B

// k-permutation within 16-blocks: pos = (k%4)*4 + (k/4)%4
__device__ __forceinline__ int kperm(int k) {
    return (k & ~15) | ((k & 3) << 2) | ((k >> 2) & 3);
}

__device__ __forceinline__ uint32_t smem_u32(const void* p) {
    uint32_t a;
    asm("{ .reg .u64 t; cvta.to.shared.u64 t, %1; cvt.u32.u64 %0, t; }"
        : "=r"(a) : "l"(p));
    return a;
}

__device__ __forceinline__ float rna_tf32_f(float f) {
    uint32_t u;
    asm("cvt.rna.tf32.f32 %0, %1;" : "=r"(u) : "f"(f));
    return __uint_as_float(u);
}

#define CP_ASYNC16(dst, src) \
    asm volatile("cp.async.cg.shared.global [%0], [%1], 16;" \
                 :: "r"(dst), "l"(src) : "memory")
#define CP_COMMIT() asm volatile("cp.async.commit_group;" ::: "memory")
#define CP_WAIT1()  asm volatile("cp.async.wait_group 1;" ::: "memory")
#define CP_WAIT2()  asm volatile("cp.async.wait_group 2;" ::: "memory")

__device__ __forceinline__ void mma_tf32(float* c, const uint32_t* a,
                                         const uint32_t* b) {
    asm volatile(
        "mma.sync.aligned.m16n8k8.row.col.f32.tf32.tf32.f32 "
        "{%0,%1,%2,%3}, {%4,%5,%6,%7}, {%8,%9}, {%0,%1,%2,%3};"
        : "+f"(c[0]), "+f"(c[1]), "+f"(c[2]), "+f"(c[3])
        : "r"(a[0]), "r"(a[1]), "r"(a[2]), "r"(a[3]), "r"(b[0]), "r"(b[1]));
}

// ---------------------------------------------------------------------------
__global__ void pack_bt_kernel(const float* __restrict__ F,
                               const float* __restrict__ G,
                               float* __restrict__ Bt) {
    __shared__ float tile[32][33];
    int kb = blockIdx.x * 32;
    int nb = blockIdx.y * 32;
    int tx = threadIdx.x, ty = threadIdx.y;   // block (32, 8)
    #pragma unroll
    for (int r = ty; r < 32; r += 8) {
        int k = kb + r, n = nb + tx;
        float v = (n < 64) ? F[(size_t)k * 64 + n] : G[(size_t)k * 64 + (n - 64)];
        tile[r][tx] = rna_tf32_f(v);
    }
    __syncthreads();
    #pragma unroll
    for (int r = ty; r < 32; r += 8) {
        int n = nb + r, k = kb + tx;
        Bt[(size_t)n * NN + kperm(k)] = tile[tx][r];
    }
}

// ---------------------------------------------------------------------------
__global__ void __launch_bounds__(256, 1)
gemm_layer(const float* __restrict__ A, const float* __restrict__ Bt,
           float* __restrict__ outT, float* __restrict__ outR) {
    extern __shared__ float smem[];
    const int tid  = threadIdx.x;
    const int lane = tid & 31;
    const int w    = tid >> 5;          // 8 warps
    const int wm   = w & 1;             // 2 warps over M
    const int wn   = w >> 1;            // 4 warps over N
    const int m0   = blockIdx.x * MT;
    const uint32_t sbase = smem_u32(smem);
    const int r4 = lane >> 2;
    const int c4 = lane & 3;

    float acc[2][4][4];
    #pragma unroll
    for (int mi = 0; mi < 2; mi++)
        #pragma unroll
        for (int ni = 0; ni < 4; ni++)
            #pragma unroll
            for (int j = 0; j < 4; j++) acc[mi][ni][j] = 0.f;

    auto issue_stage = [&](int it) {
        const int s = it & (STAGES - 1);
        const int k0 = it * KT;
        const uint32_t abase = sbase + (uint32_t)(s * STG_F) * 4u;
        const uint32_t bbase = abase + A_STG_F * 4u;
        #pragma unroll
        for (int j = 0; j < 2; j++) {
            int ch = tid + 256 * j;
            int row = ch >> 3, cc = ch & 7;
            const float* src = A + (size_t)(m0 + row) * NN + k0 + cc * 4;
            CP_ASYNC16(abase + (uint32_t)(row * AROW + cc * 4) * 4u, src);
        }
        #pragma unroll
        for (int j = 0; j < 4; j++) {
            int ch = tid + 256 * j;
            int row = ch >> 3, cc = ch & 7;
            const float* src = Bt + (size_t)row * NN + k0 + cc * 4;
            CP_ASYNC16(bbase + (uint32_t)(row * BROW + cc * 4) * 4u, src);
        }
    };

    // fragment loader for stage `it` (smem -> registers)
    auto load_frags = [&](int it, uint32_t a[4][8], float4 b[4][2]) {
        const int s = it & (STAGES - 1);
        const float* As = smem + s * STG_F;
        const float* Bs = As + A_STG_F;
        const float*  aP = As + (wm * 32 + r4) * AROW + c4;
        const float4* bP = (const float4*)(Bs + (wn * 32 + r4) * BROW) + c4;
        #pragma unroll
        for (int g = 0; g < 4; g++)
            #pragma unroll
            for (int j = 0; j < 8; j++)
                a[g][j] = __float_as_uint(aP[g * 8 * AROW + 4 * j]) + 0x1000u;
        #pragma unroll
        for (int g = 0; g < 4; g++)
            #pragma unroll
            for (int kb = 0; kb < 2; kb++)
                b[g][kb] = bP[g * 8 * (BROW / 4) + kb * 4];
    };

    auto mma_burst = [&](uint32_t a[4][8], float4 b[4][2]) {
        #pragma unroll
        for (int ks = 0; ks < 4; ks++) {
            uint32_t af0[4] = { a[0][2 * ks], a[1][2 * ks],
                                a[0][2 * ks + 1], a[1][2 * ks + 1] };
            uint32_t af1[4] = { a[2][2 * ks], a[3][2 * ks],
                                a[2][2 * ks + 1], a[3][2 * ks + 1] };
            #pragma unroll
            for (int ni = 0; ni < 4; ni++) {
                const float4 bb = b[ni][ks >> 1];
                uint32_t bf[2];
                if (ks & 1) { bf[0] = __float_as_uint(bb.z);
                              bf[1] = __float_as_uint(bb.w); }
                else        { bf[0] = __float_as_uint(bb.x);
                              bf[1] = __float_as_uint(bb.y); }
                mma_tf32(acc[0][ni], af0, bf);
                mma_tf32(acc[1][ni], af1, bf);
            }
        }
    };

    // prologue: 3 stages in flight, frags(0) resident
    issue_stage(0); CP_COMMIT();
    issue_stage(1); CP_COMMIT();
    issue_stage(2); CP_COMMIT();

    uint32_t aF[2][4][8];
    float4   bF[2][4][2];

    CP_WAIT2();
    __syncthreads();
    load_frags(0, aF[0], bF[0]);

    // one pipeline step: MMA frags(cur)=stage it, prefetch frags(it+1)
    auto step = [&](int it, uint32_t aC[4][8], float4 bC[4][2],
                    uint32_t aN[4][8], float4 bN[4][2]) {
        CP_WAIT1();                 // stage it+1 resident
        __syncthreads();            // all warps done reading stage it-1
        if (it + 3 < KIT) issue_stage(it + 3);
        CP_COMMIT();
        if (it + 1 < KIT) load_frags(it + 1, aN, bN);
        mma_burst(aC, bC);
    };

    for (int it = 0; it < KIT; it += 2) {
        step(it,     aF[0], bF[0], aF[1], bF[1]);
        step(it + 1, aF[1], bF[1], aF[0], bF[0]);
    }

    // ---- epilogue ----
    const int rBase = m0 + wm * 32 + r4;
    const int nBase = wn * 32 + c4 * 2;
    #pragma unroll
    for (int mi = 0; mi < 2; mi++) {
        #pragma unroll
        for (int ni = 0; ni < 4; ni++) {
            #pragma unroll
            for (int j = 0; j < 4; j++) {
                int row = rBase + mi * 16 + (j >> 1) * 8;
                int col = nBase + ni * 8 + (j & 1);
                float v = acc[mi][ni][j];
                if (col < 64) v = fmaxf(v, 0.0f);
                if (outT) outT[(size_t)col * NN + kperm(row)] = rna_tf32_f(v);
                else      outR[(size_t)row * NB + col] = v;
            }
        }
    }
}

// ---------------------------------------------------------------------------
extern "C" void kernel_launch(void* const* d_in, const int* in_sizes, int n_in,
                              void* d_out, int out_size) {
    (void)in_sizes; (void)n_in; (void)out_size;
    const float* A = (const float*)d_in[0];
    const float* F = (const float*)d_in[1];
    const float* G = (const float*)d_in[2];
    float* out = (float*)d_out;

    float *bt1 = nullptr, *bt2 = nullptr;
    cudaGetSymbolAddress((void**)&bt1, g_bt1);
    cudaGetSymbolAddress((void**)&bt2, g_bt2);

    cudaFuncSetAttribute(gemm_layer,
                         cudaFuncAttributeMaxDynamicSharedMemorySize, SMEM_BYTES);

    dim3 pb(32, 8), pg(NN / 32, NB / 32);
    pack_bt_kernel<<<pg, pb>>>(F, G, bt1);

    gemm_layer<<<NN / MT, 256, SMEM_BYTES>>>(A, bt1, bt2, nullptr);
    gemm_layer<<<NN / MT, 256, SMEM_BYTES>>>(A, bt2, nullptr, out);
}